// round 4
// baseline (speedup 1.0000x reference)
#include <cuda_runtime.h>
#include <math.h>

#define H      2048
#define HH     1024
#define NB     4
#define S      4096
#define NROWS  (NB*S)          // 16384 rows per matrix
#define SCHUNK 64
#define NCHUNK (S/SCHUNK)      // 64
#define TILE_R 16
#define MT     256             // main kernel threads

typedef unsigned long long ull;

// ---------------- packed f32x2 helpers ----------------------------------
__device__ __forceinline__ ull pack2(float lo, float hi) {
    ull r; asm("mov.b64 %0, {%1, %2};" : "=l"(r) : "f"(lo), "f"(hi)); return r;
}
__device__ __forceinline__ ull fma2(ull a, ull b, ull c) {
    ull d; asm("fma.rn.f32x2 %0, %1, %2, %3;" : "=l"(d) : "l"(a), "l"(b), "l"(c)); return d;
}
__device__ __forceinline__ float pairsum(ull a) {
    float lo, hi; asm("mov.b64 {%0, %1}, %2;" : "=f"(lo), "=f"(hi) : "l"(a)); return lo + hi;
}

// ---------------- device scratch (no allocation allowed) ----------------
__device__ float g_partial[NB*NCHUNK*H];   // fully overwritten each call
__device__ float g_h1p[NB*8*HH];
__device__ int   g_rank;
__device__ float g_At[2*16*H];             // kA^T at 0, vA^T at 16*H (selected rank)

// ---------------- kernel 1: chunked column sums of keys over S ----------
__global__ void k_mean_partial(const float* __restrict__ keys) {
    int b = blockIdx.y, c = blockIdx.x;
    const float4* base = (const float4*)(keys + ((size_t)b * S + (size_t)c * SCHUNK) * H);
    int t = threadIdx.x;                    // 512 threads cover H/4 float4 cols
    float4 a = make_float4(0.f, 0.f, 0.f, 0.f);
#pragma unroll 8
    for (int s = 0; s < SCHUNK; s++) {
        float4 v = __ldcg(base + (size_t)s * (H / 4) + t);
        a.x += v.x; a.y += v.y; a.z += v.z; a.w += v.w;
    }
    ((float4*)(g_partial + ((size_t)b * NCHUNK + c) * H))[t] = a;
}

// ---------------- kernel 2: hidden GEMV, w1 read once ---------------------
// grid (4 jb, 8 hc), 256 threads. Accumulates all NB batches per thread.
__global__ void k_gemv1(const float* __restrict__ w1) {
    __shared__ float sx[NB][256];
    int jb = blockIdx.x, hc = blockIdx.y;
    int t = threadIdx.x;
    int h = hc * 256 + t;
#pragma unroll
    for (int b = 0; b < NB; b++) {
        float s0 = 0.f, s1 = 0.f, s2 = 0.f, s3 = 0.f;
#pragma unroll
        for (int c = 0; c < NCHUNK; c += 4) {
            s0 += g_partial[((size_t)b * NCHUNK + c + 0) * H + h];
            s1 += g_partial[((size_t)b * NCHUNK + c + 1) * H + h];
            s2 += g_partial[((size_t)b * NCHUNK + c + 2) * H + h];
            s3 += g_partial[((size_t)b * NCHUNK + c + 3) * H + h];
        }
        sx[b][t] = (s0 + s1 + s2 + s3) * (1.0f / (float)S);
    }
    __syncthreads();
    int j = jb * 256 + t;
    const float* wp = w1 + (size_t)(hc * 256) * HH + j;
    float a0 = 0.f, a1 = 0.f, a2 = 0.f, a3 = 0.f;
#pragma unroll 4
    for (int hh = 0; hh < 256; hh++) {
        float w = wp[(size_t)hh * HH];
        a0 = fmaf(sx[0][hh], w, a0);
        a1 = fmaf(sx[1][hh], w, a1);
        a2 = fmaf(sx[2][hh], w, a2);
        a3 = fmaf(sx[3][hh], w, a3);
    }
    g_h1p[((size_t)0 * 8 + hc) * HH + j] = a0;
    g_h1p[((size_t)1 * 8 + hc) * HH + j] = a1;
    g_h1p[((size_t)2 * 8 + hc) * HH + j] = a2;
    g_h1p[((size_t)3 * 8 + hc) * HH + j] = a3;
}

// ---------------- kernel 3: relu + layer2 + sigmoid + rank select -------
__global__ void k_select(const float* __restrict__ b1, const float* __restrict__ w2,
                         const float* __restrict__ b2) {
    __shared__ float red[256];
    __shared__ float s_avg;
    int t = threadIdx.x;
    if (t == 0) s_avg = 0.f;
    __syncthreads();
    for (int b = 0; b < NB; b++) {
        float acc = 0.f;
#pragma unroll
        for (int k = 0; k < 4; k++) {
            int j = t + k * 256;
            float hv = b1[j];
#pragma unroll
            for (int hc = 0; hc < 8; hc++) hv += g_h1p[((size_t)b * 8 + hc) * HH + j];
            acc += fmaxf(hv, 0.f) * w2[j];
        }
        red[t] = acc;
        __syncthreads();
        for (int o = 128; o > 0; o >>= 1) {
            if (t < o) red[t] += red[t + o];
            __syncthreads();
        }
        if (t == 0) {
            float v = red[0] + b2[0];
            s_avg += 1.f / (1.f + expf(-v));
        }
        __syncthreads();
    }
    if (t == 0) {
        float avg = s_avg * 0.25f;
        g_rank = (int)(avg >= 0.3f) + (int)(avg >= 0.7f);
    }
}

// ---------------- kernel 4: transpose selected A's into g_At ------------
__global__ void k_prep(const float* __restrict__ kA0, const float* __restrict__ vA0,
                       const float* __restrict__ kA1, const float* __restrict__ vA1,
                       const float* __restrict__ kA2, const float* __restrict__ vA2) {
    int r = g_rank;
    const float* kA = (r == 0) ? kA0 : (r == 1) ? kA1 : kA2;
    const float* vA = (r == 0) ? vA0 : (r == 1) ? vA1 : vA2;
    int R = 4 << r;
    int total = R * H;
    for (int idx = blockIdx.x * blockDim.x + threadIdx.x; idx < total;
         idx += gridDim.x * blockDim.x) {
        int j = idx / H, h = idx - j * H;          // g_At[j*H + h] = A[h*R + j]
        g_At[idx]          = kA[(size_t)h * R + j];
        g_At[16 * H + idx] = vA[(size_t)h * R + j];
    }
}

// ---------------- main body: out = x + (x @ A) @ B ----------------------
template <int R>
__device__ __forceinline__ void main_body(
    const float* __restrict__ src, const float* __restrict__ At,
    const float* __restrict__ Bw, float* __restrict__ dst,
    int row0, float* s_P2) {

    int tid = threadIdx.x;
    int w = tid >> 5, l = tid & 31;

    // ---- Phase 1: P[row][j] = row . A^T[j]; 1 row per warp, 2 passes ---
#pragma unroll
    for (int ps = 0; ps < 2; ps++) {
        int r_i = ps * 8 + w;
        const float4* rp = (const float4*)(src + (size_t)(row0 + r_i) * H);
        ull acc[R];
#pragma unroll
        for (int j = 0; j < R; j++) acc[j] = 0ull;

#pragma unroll 4
        for (int h4 = l; h4 < H / 4; h4 += 32) {
            float4 v = __ldcg(rp + h4);
            ull kx = pack2(v.x, v.y), ky = pack2(v.z, v.w);
#pragma unroll
            for (int j = 0; j < R; j++) {
                float4 av = __ldg((const float4*)(At + (size_t)j * H + h4 * 4));
                acc[j] = fma2(kx, pack2(av.x, av.y), acc[j]);
                acc[j] = fma2(ky, pack2(av.z, av.w), acc[j]);
            }
        }
#pragma unroll
        for (int j = 0; j < R; j++) {
            float v = pairsum(acc[j]);
#pragma unroll
            for (int o = 16; o > 0; o >>= 1) v += __shfl_xor_sync(0xffffffffu, v, o);
            if (l == 0) *(ull*)(s_P2 + (r_i * R + j) * 2) = pack2(v, v);
        }
    }
    __syncthreads();

    // ---- Phase 2: out[row][h] = src[row][h] + sum_j P[row][j]*B[j][h] ---
    // Two column halves; 4-row groups for MLP.
#pragma unroll
    for (int cs = 0; cs < 2; cs++) {
        int col4 = tid + cs * MT;                 // float4 column in [0, 512)
        ull b0[(R <= 8) ? R : 1], b1[(R <= 8) ? R : 1];
        if (R <= 8) {
#pragma unroll
            for (int j = 0; j < R; j++) {
                float4 bv = __ldg((const float4*)(Bw + (size_t)j * H + col4 * 4));
                b0[j] = pack2(bv.x, bv.y); b1[j] = pack2(bv.z, bv.w);
            }
        }
#pragma unroll
        for (int g = 0; g < TILE_R; g += 4) {
            float4 v0 = __ldcg((const float4*)(src + (size_t)(row0 + g + 0) * H + col4 * 4));
            float4 v1 = __ldcg((const float4*)(src + (size_t)(row0 + g + 1) * H + col4 * 4));
            float4 v2 = __ldcg((const float4*)(src + (size_t)(row0 + g + 2) * H + col4 * 4));
            float4 v3 = __ldcg((const float4*)(src + (size_t)(row0 + g + 3) * H + col4 * 4));
            ull o0x = pack2(v0.x, v0.y), o0y = pack2(v0.z, v0.w);
            ull o1x = pack2(v1.x, v1.y), o1y = pack2(v1.z, v1.w);
            ull o2x = pack2(v2.x, v2.y), o2y = pack2(v2.z, v2.w);
            ull o3x = pack2(v3.x, v3.y), o3y = pack2(v3.z, v3.w);
#pragma unroll
            for (int j = 0; j < R; j++) {
                ull bx, by;
                if (R <= 8) { bx = b0[j]; by = b1[j]; }
                else {
                    float4 bv = __ldg((const float4*)(Bw + (size_t)j * H + col4 * 4));
                    bx = pack2(bv.x, bv.y); by = pack2(bv.z, bv.w);
                }
                ull p0 = *(const ull*)(s_P2 + ((g + 0) * R + j) * 2);
                ull p1 = *(const ull*)(s_P2 + ((g + 1) * R + j) * 2);
                ull p2 = *(const ull*)(s_P2 + ((g + 2) * R + j) * 2);
                ull p3 = *(const ull*)(s_P2 + ((g + 3) * R + j) * 2);
                o0x = fma2(bx, p0, o0x); o0y = fma2(by, p0, o0y);
                o1x = fma2(bx, p1, o1x); o1y = fma2(by, p1, o1y);
                o2x = fma2(bx, p2, o2x); o2y = fma2(by, p2, o2y);
                o3x = fma2(bx, p3, o3x); o3y = fma2(by, p3, o3y);
            }
            float r0, r1, r2, r3;
#define STORE_ROW(OX, OY, GG)                                                        \
            asm("mov.b64 {%0, %1}, %2;" : "=f"(r0), "=f"(r1) : "l"(OX));             \
            asm("mov.b64 {%0, %1}, %2;" : "=f"(r2), "=f"(r3) : "l"(OY));             \
            __stcg((float4*)(dst + (size_t)(row0 + GG) * H + col4 * 4),              \
                   make_float4(r0, r1, r2, r3));
            STORE_ROW(o0x, o0y, g + 0)
            STORE_ROW(o1x, o1y, g + 1)
            STORE_ROW(o2x, o2y, g + 2)
            STORE_ROW(o3x, o3y, g + 3)
#undef STORE_ROW
        }
    }
}

// single kernel, uniform branch on g_rank — no dead launches
__global__ void __launch_bounds__(MT, 3)
k_main_all(const float* __restrict__ keys, const float* __restrict__ values,
           const float* __restrict__ kB0, const float* __restrict__ kB1,
           const float* __restrict__ kB2,
           const float* __restrict__ vB0, const float* __restrict__ vB1,
           const float* __restrict__ vB2,
           float* __restrict__ out) {
    __shared__ float s_P2[TILE_R * 16 * 2];
    int r = g_rank;
    int row0 = blockIdx.x * TILE_R;
    const float* src; const float* At; float* dst; bool is_k;
    if (row0 < NROWS) { src = keys;   At = g_At;           dst = out;                      is_k = true; }
    else { row0 -= NROWS; src = values; At = g_At + 16 * H; dst = out + (size_t)NROWS * H; is_k = false; }

    if (r == 0) {
        main_body<4>(src, At, is_k ? kB0 : vB0, dst, row0, s_P2);
    } else if (r == 1) {
        main_body<8>(src, At, is_k ? kB1 : vB1, dst, row0, s_P2);
    } else {
        main_body<16>(src, At, is_k ? kB2 : vB2, dst, row0, s_P2);
    }
}

// ---------------- launch -------------------------------------------------
extern "C" void kernel_launch(void* const* d_in, const int* in_sizes, int n_in,
                              void* d_out, int out_size) {
    const float* keys   = (const float*)d_in[0];
    const float* values = (const float*)d_in[1];
    const float* w1     = (const float*)d_in[2];
    const float* b1     = (const float*)d_in[3];
    const float* w2     = (const float*)d_in[4];
    const float* b2     = (const float*)d_in[5];
    const float* kA0 = (const float*)d_in[6];  const float* kB0 = (const float*)d_in[7];
    const float* vA0 = (const float*)d_in[8];  const float* vB0 = (const float*)d_in[9];
    const float* kA1 = (const float*)d_in[10]; const float* kB1 = (const float*)d_in[11];
    const float* vA1 = (const float*)d_in[12]; const float* vB1 = (const float*)d_in[13];
    const float* kA2 = (const float*)d_in[14]; const float* kB2 = (const float*)d_in[15];
    const float* vA2 = (const float*)d_in[16]; const float* vB2 = (const float*)d_in[17];
    float* out = (float*)d_out;

    k_mean_partial<<<dim3(NCHUNK, NB), 512>>>(keys);
    k_gemv1<<<dim3(4, 8), 256>>>(w1);
    k_select<<<1, 256>>>(b1, w2, b2);
    k_prep<<<48, 256>>>(kA0, vA0, kA1, vA1, kA2, vA2);

    const int grid = (2 * NROWS) / TILE_R;   // 2048 CTAs
    k_main_all<<<grid, MT>>>(keys, values, kB0, kB1, kB2, vB0, vB1, vB2, out);
}

// round 5
// speedup vs baseline: 1.9423x; 1.9423x over previous
#include <cuda_runtime.h>
#include <math.h>

#define H      2048
#define HH     1024
#define NB     4
#define S      4096
#define NROWS  (NB*S)          // 16384 rows per matrix
#define SCHUNK 64
#define NCHUNK (S/SCHUNK)      // 64
#define TILE_R 32
#define MT     512             // main kernel threads

typedef unsigned long long ull;

// ---------------- packed f32x2 helpers ----------------------------------
__device__ __forceinline__ ull pack2(float lo, float hi) {
    ull r; asm("mov.b64 %0, {%1, %2};" : "=l"(r) : "f"(lo), "f"(hi)); return r;
}
__device__ __forceinline__ ull fma2(ull a, ull b, ull c) {
    ull d; asm("fma.rn.f32x2 %0, %1, %2, %3;" : "=l"(d) : "l"(a), "l"(b), "l"(c)); return d;
}
__device__ __forceinline__ float pairsum(ull a) {
    float lo, hi; asm("mov.b64 {%0, %1}, %2;" : "=f"(lo), "=f"(hi) : "l"(a)); return lo + hi;
}

// ---------------- device scratch (no allocation allowed) ----------------
__device__ float g_partial[NB*NCHUNK*H];   // fully overwritten each call
__device__ float g_h1p[NB*8*HH];
__device__ int   g_rank;

// ---------------- kernel 1: chunked column sums of keys over S ----------
__global__ void k_mean_partial(const float* __restrict__ keys) {
    int b = blockIdx.y, c = blockIdx.x;
    const float4* base = (const float4*)(keys + ((size_t)b * S + (size_t)c * SCHUNK) * H);
    int t = threadIdx.x;                    // 512 threads cover H/4 float4 cols
    float4 a = make_float4(0.f, 0.f, 0.f, 0.f);
#pragma unroll 4
    for (int s = 0; s < SCHUNK; s++) {
        float4 v = base[(size_t)s * (H / 4) + t];
        a.x += v.x; a.y += v.y; a.z += v.z; a.w += v.w;
    }
    ((float4*)(g_partial + ((size_t)b * NCHUNK + c) * H))[t] = a;
}

// ---------------- kernel 2: hidden GEMV, w1 read once --------------------
__global__ void k_gemv1(const float* __restrict__ w1) {
    __shared__ float sx[NB][256];
    int jb = blockIdx.x, hc = blockIdx.y;
    int t = threadIdx.x;
    int h = hc * 256 + t;
#pragma unroll
    for (int b = 0; b < NB; b++) {
        float s0 = 0.f, s1 = 0.f, s2 = 0.f, s3 = 0.f;
#pragma unroll
        for (int c = 0; c < NCHUNK; c += 4) {
            s0 += g_partial[((size_t)b * NCHUNK + c + 0) * H + h];
            s1 += g_partial[((size_t)b * NCHUNK + c + 1) * H + h];
            s2 += g_partial[((size_t)b * NCHUNK + c + 2) * H + h];
            s3 += g_partial[((size_t)b * NCHUNK + c + 3) * H + h];
        }
        sx[b][t] = (s0 + s1 + s2 + s3) * (1.0f / (float)S);
    }
    __syncthreads();
    int j = jb * 256 + t;
    const float* wp = w1 + (size_t)(hc * 256) * HH + j;
    float a0 = 0.f, a1 = 0.f, a2 = 0.f, a3 = 0.f;
#pragma unroll 4
    for (int hh = 0; hh < 256; hh++) {
        float w = wp[(size_t)hh * HH];
        a0 = fmaf(sx[0][hh], w, a0);
        a1 = fmaf(sx[1][hh], w, a1);
        a2 = fmaf(sx[2][hh], w, a2);
        a3 = fmaf(sx[3][hh], w, a3);
    }
    g_h1p[((size_t)0 * 8 + hc) * HH + j] = a0;
    g_h1p[((size_t)1 * 8 + hc) * HH + j] = a1;
    g_h1p[((size_t)2 * 8 + hc) * HH + j] = a2;
    g_h1p[((size_t)3 * 8 + hc) * HH + j] = a3;
}

// ---------------- kernel 3: relu + layer2 + sigmoid + rank select -------
__global__ void k_select(const float* __restrict__ b1, const float* __restrict__ w2,
                         const float* __restrict__ b2) {
    __shared__ float red[256];
    __shared__ float s_avg;
    int t = threadIdx.x;
    if (t == 0) s_avg = 0.f;
    __syncthreads();
    for (int b = 0; b < NB; b++) {
        float acc = 0.f;
#pragma unroll
        for (int k = 0; k < 4; k++) {
            int j = t + k * 256;
            float hv = b1[j];
#pragma unroll
            for (int hc = 0; hc < 8; hc++) hv += g_h1p[((size_t)b * 8 + hc) * HH + j];
            acc += fmaxf(hv, 0.f) * w2[j];
        }
        red[t] = acc;
        __syncthreads();
        for (int o = 128; o > 0; o >>= 1) {
            if (t < o) red[t] += red[t + o];
            __syncthreads();
        }
        if (t == 0) {
            float v = red[0] + b2[0];
            s_avg += 1.f / (1.f + expf(-v));
        }
        __syncthreads();
    }
    if (t == 0) {
        float avg = s_avg * 0.25f;
        g_rank = (int)(avg >= 0.3f) + (int)(avg >= 0.7f);
    }
}

// ======================= main kernel bodies ==============================
// smem layout: s_w = 8*H floats (weight buffer), s_P2 = TILE_R*16*2 floats.

// ---- hot path: R <= 8, weights fit the buffer ---------------------------
template <int R>
__device__ __forceinline__ void main_body(
    const float* __restrict__ src, const float* __restrict__ A,
    const float* __restrict__ Bw, float* __restrict__ dst,
    int row0, float* s_w, float* s_P2) {

    int tid = threadIdx.x;
    int w = tid >> 5, l = tid & 31;
    constexpr int SH = (R == 4) ? 2 : 3;

    // stage A transposed: s_w[j*H + h] = A[h*R + j]
    for (int idx = tid; idx < H * R; idx += MT) {
        int h = idx >> SH, j = idx & (R - 1);
        s_w[j * H + h] = A[idx];
    }
    __syncthreads();

    // ---- Phase 1: 16 warps x 2 rows ------------------------------------
    {
        ull acc[2][R];
#pragma unroll
        for (int i = 0; i < 2; i++)
#pragma unroll
            for (int j = 0; j < R; j++) acc[i][j] = 0ull;

        const ulonglong2* rp0 = (const ulonglong2*)(src + (size_t)(row0 + w * 2 + 0) * H);
        const ulonglong2* rp1 = (const ulonglong2*)(src + (size_t)(row0 + w * 2 + 1) * H);

#pragma unroll 2
        for (int h4 = l; h4 < H / 4; h4 += 32) {
            ulonglong2 k0 = rp0[h4], k1 = rp1[h4];
#pragma unroll
            for (int j = 0; j < R; j++) {
                ulonglong2 aq = *(const ulonglong2*)(s_w + j * H + h4 * 4);
                acc[0][j] = fma2(k0.x, aq.x, acc[0][j]);
                acc[0][j] = fma2(k0.y, aq.y, acc[0][j]);
                acc[1][j] = fma2(k1.x, aq.x, acc[1][j]);
                acc[1][j] = fma2(k1.y, aq.y, acc[1][j]);
            }
        }
#pragma unroll
        for (int i = 0; i < 2; i++)
#pragma unroll
            for (int j = 0; j < R; j++) {
                float v = pairsum(acc[i][j]);
#pragma unroll
                for (int o = 16; o > 0; o >>= 1) v += __shfl_xor_sync(0xffffffffu, v, o);
                if (l == 0) *(ull*)(s_P2 + ((w * 2 + i) * R + j) * 2) = pack2(v, v);
            }
    }
    __syncthreads();

    // stage B (straight copy) into the same buffer
    for (int idx = tid; idx < R * H; idx += MT) s_w[idx] = Bw[idx];
    __syncthreads();

    // ---- Phase 2: thread owns float4-column tid; 4-row groups ----------
#pragma unroll 1
    for (int g = 0; g < TILE_R; g += 4) {
        ulonglong2 o0 = ((const ulonglong2*)(src + (size_t)(row0 + g + 0) * H))[tid];
        ulonglong2 o1 = ((const ulonglong2*)(src + (size_t)(row0 + g + 1) * H))[tid];
        ulonglong2 o2 = ((const ulonglong2*)(src + (size_t)(row0 + g + 2) * H))[tid];
        ulonglong2 o3 = ((const ulonglong2*)(src + (size_t)(row0 + g + 3) * H))[tid];
#pragma unroll
        for (int j = 0; j < R; j++) {
            ulonglong2 bq = *(const ulonglong2*)(s_w + j * H + tid * 4);
            ull p0 = *(const ull*)(s_P2 + ((g + 0) * R + j) * 2);
            ull p1 = *(const ull*)(s_P2 + ((g + 1) * R + j) * 2);
            ull p2 = *(const ull*)(s_P2 + ((g + 2) * R + j) * 2);
            ull p3 = *(const ull*)(s_P2 + ((g + 3) * R + j) * 2);
            o0.x = fma2(bq.x, p0, o0.x); o0.y = fma2(bq.y, p0, o0.y);
            o1.x = fma2(bq.x, p1, o1.x); o1.y = fma2(bq.y, p1, o1.y);
            o2.x = fma2(bq.x, p2, o2.x); o2.y = fma2(bq.y, p2, o2.y);
            o3.x = fma2(bq.x, p3, o3.x); o3.y = fma2(bq.y, p3, o3.y);
        }
        ((ulonglong2*)(dst + (size_t)(row0 + g + 0) * H))[tid] = o0;
        ((ulonglong2*)(dst + (size_t)(row0 + g + 1) * H))[tid] = o1;
        ((ulonglong2*)(dst + (size_t)(row0 + g + 2) * H))[tid] = o2;
        ((ulonglong2*)(dst + (size_t)(row0 + g + 3) * H))[tid] = o3;
    }
}

// ---- cold path: R = 16 via two 8-wide halves (correct, rarely taken) ---
__device__ __noinline__ void main_body16(
    const float* __restrict__ src, const float* __restrict__ A,
    const float* __restrict__ Bw, float* __restrict__ dst,
    int row0, float* s_w, float* s_P2) {

    int tid = threadIdx.x;
    int w = tid >> 5, l = tid & 31;
    constexpr int R = 16;

    // Phase 1 in two halves of 8 j-columns
    for (int half = 0; half < 2; half++) {
        for (int idx = tid; idx < H * 8; idx += MT) {
            int h = idx >> 3, j = idx & 7;
            s_w[j * H + h] = A[(size_t)h * R + half * 8 + j];
        }
        __syncthreads();
        ull acc[2][8];
#pragma unroll
        for (int i = 0; i < 2; i++)
#pragma unroll
            for (int j = 0; j < 8; j++) acc[i][j] = 0ull;
        const ulonglong2* rp0 = (const ulonglong2*)(src + (size_t)(row0 + w * 2 + 0) * H);
        const ulonglong2* rp1 = (const ulonglong2*)(src + (size_t)(row0 + w * 2 + 1) * H);
        for (int h4 = l; h4 < H / 4; h4 += 32) {
            ulonglong2 k0 = rp0[h4], k1 = rp1[h4];
#pragma unroll
            for (int j = 0; j < 8; j++) {
                ulonglong2 aq = *(const ulonglong2*)(s_w + j * H + h4 * 4);
                acc[0][j] = fma2(k0.x, aq.x, acc[0][j]);
                acc[0][j] = fma2(k0.y, aq.y, acc[0][j]);
                acc[1][j] = fma2(k1.x, aq.x, acc[1][j]);
                acc[1][j] = fma2(k1.y, aq.y, acc[1][j]);
            }
        }
#pragma unroll
        for (int i = 0; i < 2; i++)
#pragma unroll
            for (int j = 0; j < 8; j++) {
                float v = pairsum(acc[i][j]);
#pragma unroll
                for (int o = 16; o > 0; o >>= 1) v += __shfl_xor_sync(0xffffffffu, v, o);
                if (l == 0)
                    *(ull*)(s_P2 + ((w * 2 + i) * R + half * 8 + j) * 2) = pack2(v, v);
            }
        __syncthreads();
    }

    // Phase 2 in two halves of 8 B-rows; half 1 accumulates onto dst.
    for (int half = 0; half < 2; half++) {
        for (int idx = tid; idx < 8 * H; idx += MT) s_w[idx] = Bw[half * 8 * H + idx];
        __syncthreads();
        for (int g = 0; g < TILE_R; g += 2) {
            const float* base0 = half ? dst : src;
            ulonglong2 o0 = ((const ulonglong2*)(base0 + (size_t)(row0 + g + 0) * H))[tid];
            ulonglong2 o1 = ((const ulonglong2*)(base0 + (size_t)(row0 + g + 1) * H))[tid];
#pragma unroll
            for (int j = 0; j < 8; j++) {
                ulonglong2 bq = *(const ulonglong2*)(s_w + j * H + tid * 4);
                ull p0 = *(const ull*)(s_P2 + ((g + 0) * R + half * 8 + j) * 2);
                ull p1 = *(const ull*)(s_P2 + ((g + 1) * R + half * 8 + j) * 2);
                o0.x = fma2(bq.x, p0, o0.x); o0.y = fma2(bq.y, p0, o0.y);
                o1.x = fma2(bq.x, p1, o1.x); o1.y = fma2(bq.y, p1, o1.y);
            }
            ((ulonglong2*)(dst + (size_t)(row0 + g + 0) * H))[tid] = o0;
            ((ulonglong2*)(dst + (size_t)(row0 + g + 1) * H))[tid] = o1;
        }
        __syncthreads();
    }
}

// single kernel, uniform branch on g_rank — no dead launches
__global__ void __launch_bounds__(MT, 2)
k_main_all(const float* __restrict__ keys, const float* __restrict__ values,
           const float* __restrict__ kA0, const float* __restrict__ kB0,
           const float* __restrict__ vA0, const float* __restrict__ vB0,
           const float* __restrict__ kA1, const float* __restrict__ kB1,
           const float* __restrict__ vA1, const float* __restrict__ vB1,
           const float* __restrict__ kA2, const float* __restrict__ kB2,
           const float* __restrict__ vA2, const float* __restrict__ vB2,
           float* __restrict__ out) {
    extern __shared__ float smem[];
    float* s_w  = smem;                 // 8*H floats
    float* s_P2 = smem + 8 * H;         // TILE_R*16*2 floats

    int r = g_rank;
    int row0 = blockIdx.x * TILE_R;
    const float* src; float* dst; bool is_k;
    if (row0 < NROWS) { src = keys;   dst = out;                       is_k = true; }
    else { row0 -= NROWS; src = values; dst = out + (size_t)NROWS * H; is_k = false; }

    if (r == 0)
        main_body<4>(src, is_k ? kA0 : vA0, is_k ? kB0 : vB0, dst, row0, s_w, s_P2);
    else if (r == 1)
        main_body<8>(src, is_k ? kA1 : vA1, is_k ? kB1 : vB1, dst, row0, s_w, s_P2);
    else
        main_body16(src, is_k ? kA2 : vA2, is_k ? kB2 : vB2, dst, row0, s_w, s_P2);
}

// ---------------- launch -------------------------------------------------
extern "C" void kernel_launch(void* const* d_in, const int* in_sizes, int n_in,
                              void* d_out, int out_size) {
    const float* keys   = (const float*)d_in[0];
    const float* values = (const float*)d_in[1];
    const float* w1     = (const float*)d_in[2];
    const float* b1     = (const float*)d_in[3];
    const float* w2     = (const float*)d_in[4];
    const float* b2     = (const float*)d_in[5];
    const float* kA0 = (const float*)d_in[6];  const float* kB0 = (const float*)d_in[7];
    const float* vA0 = (const float*)d_in[8];  const float* vB0 = (const float*)d_in[9];
    const float* kA1 = (const float*)d_in[10]; const float* kB1 = (const float*)d_in[11];
    const float* vA1 = (const float*)d_in[12]; const float* vB1 = (const float*)d_in[13];
    const float* kA2 = (const float*)d_in[14]; const float* kB2 = (const float*)d_in[15];
    const float* vA2 = (const float*)d_in[16]; const float* vB2 = (const float*)d_in[17];
    float* out = (float*)d_out;

    const int smem_bytes = (8 * H + TILE_R * 16 * 2) * (int)sizeof(float);  // 69,632
    cudaFuncSetAttribute(k_main_all, cudaFuncAttributeMaxDynamicSharedMemorySize, smem_bytes);

    k_mean_partial<<<dim3(NCHUNK, NB), 512>>>(keys);
    k_gemv1<<<dim3(4, 8), 256>>>(w1);
    k_select<<<1, 256>>>(b1, w2, b2);

    const int grid = (2 * NROWS) / TILE_R;   // 1024 CTAs
    k_main_all<<<grid, MT, smem_bytes>>>(
        keys, values,
        kA0, kB0, vA0, vB0,
        kA1, kB1, vA1, vB1,
        kA2, kB2, vA2, vB2,
        out);
}

// round 6
// speedup vs baseline: 2.1813x; 1.1230x over previous
#include <cuda_runtime.h>
#include <math.h>

#define H      2048
#define HH     1024
#define NB     4
#define S      4096
#define NROWS  (NB*S)          // 16384 rows per matrix
#define SCHUNK 32
#define NCHUNK (S/SCHUNK)      // 128
#define TILE_R 32
#define MT     256             // main kernel threads

typedef unsigned long long ull;

// ---------------- packed f32x2 helpers ----------------------------------
__device__ __forceinline__ ull pack2(float lo, float hi) {
    ull r; asm("mov.b64 %0, {%1, %2};" : "=l"(r) : "f"(lo), "f"(hi)); return r;
}
__device__ __forceinline__ ull fma2(ull a, ull b, ull c) {
    ull d; asm("fma.rn.f32x2 %0, %1, %2, %3;" : "=l"(d) : "l"(a), "l"(b), "l"(c)); return d;
}
__device__ __forceinline__ float pairsum(ull a) {
    float lo, hi; asm("mov.b64 {%0, %1}, %2;" : "=f"(lo), "=f"(hi) : "l"(a)); return lo + hi;
}

// ---------------- device scratch (no allocation allowed) ----------------
__device__ float g_partial[NB*NCHUNK*H];   // 4 MB, fully overwritten each call
__device__ float g_h1p[NB*8*HH];
__device__ int   g_rank;

// ---------------- kernel 1: chunked column sums of keys over S ----------
__global__ void k_mean_partial(const float* __restrict__ keys) {
    int b = blockIdx.y, c = blockIdx.x;
    const float4* base = (const float4*)(keys + ((size_t)b * S + (size_t)c * SCHUNK) * H);
    int t = threadIdx.x;                    // 512 threads cover H/4 float4 cols
    float4 a = make_float4(0.f, 0.f, 0.f, 0.f);
#pragma unroll 8
    for (int s = 0; s < SCHUNK; s++) {
        float4 v = base[(size_t)s * (H / 4) + t];
        a.x += v.x; a.y += v.y; a.z += v.z; a.w += v.w;
    }
    ((float4*)(g_partial + ((size_t)b * NCHUNK + c) * H))[t] = a;
}

// ---------------- kernel 2: partial hidden GEMV (parallel over b) -------
__global__ void k_gemv1(const float* __restrict__ w1) {
    __shared__ float sx[256];
    int jb = blockIdx.x, hc = blockIdx.y, b = blockIdx.z;
    int t = threadIdx.x;
    {
        int h = hc * 256 + t;
        float s0 = 0.f, s1 = 0.f, s2 = 0.f, s3 = 0.f;
#pragma unroll 8
        for (int c = 0; c < NCHUNK; c += 4) {
            s0 += g_partial[((size_t)b * NCHUNK + c + 0) * H + h];
            s1 += g_partial[((size_t)b * NCHUNK + c + 1) * H + h];
            s2 += g_partial[((size_t)b * NCHUNK + c + 2) * H + h];
            s3 += g_partial[((size_t)b * NCHUNK + c + 3) * H + h];
        }
        sx[t] = (s0 + s1 + s2 + s3) * (1.0f / (float)S);
    }
    __syncthreads();
    int j = jb * 256 + t;
    const float* wp = w1 + (size_t)(hc * 256) * HH + j;
    float a0 = 0.f, a1 = 0.f, a2 = 0.f, a3 = 0.f;
#pragma unroll 8
    for (int hh = 0; hh < 256; hh += 4) {
        a0 = fmaf(sx[hh + 0], wp[(size_t)(hh + 0) * HH], a0);
        a1 = fmaf(sx[hh + 1], wp[(size_t)(hh + 1) * HH], a1);
        a2 = fmaf(sx[hh + 2], wp[(size_t)(hh + 2) * HH], a2);
        a3 = fmaf(sx[hh + 3], wp[(size_t)(hh + 3) * HH], a3);
    }
    g_h1p[((size_t)b * 8 + hc) * HH + j] = (a0 + a1) + (a2 + a3);
}

// ---------------- kernel 3: relu + layer2 + sigmoid + rank select -------
__global__ void k_select(const float* __restrict__ b1, const float* __restrict__ w2,
                         const float* __restrict__ b2) {
    __shared__ float red[256];
    __shared__ float s_avg;
    int t = threadIdx.x;
    if (t == 0) s_avg = 0.f;
    __syncthreads();
    for (int b = 0; b < NB; b++) {
        float acc = 0.f;
#pragma unroll
        for (int k = 0; k < 4; k++) {
            int j = t + k * 256;
            float hv = b1[j];
#pragma unroll
            for (int hc = 0; hc < 8; hc++) hv += g_h1p[((size_t)b * 8 + hc) * HH + j];
            acc += fmaxf(hv, 0.f) * w2[j];
        }
        red[t] = acc;
        __syncthreads();
        for (int o = 128; o > 0; o >>= 1) {
            if (t < o) red[t] += red[t + o];
            __syncthreads();
        }
        if (t == 0) {
            float v = red[0] + b2[0];
            s_avg += 1.f / (1.f + expf(-v));
        }
        __syncthreads();
    }
    if (t == 0) {
        float avg = s_avg * 0.25f;
        g_rank = (int)(avg >= 0.3f) + (int)(avg >= 0.7f);
    }
}

// ======================= main kernel =====================================
// smem: s_w = 8*H floats (A^T buffer), s_P2 = TILE_R*16*2 floats.
// 256 threads, 8 warps; phase 1: warp handles 4 rows; phase 2: thread owns
// 2 float4 columns, B hoisted in registers straight from global (L2-hot).

template <int R>
__device__ __forceinline__ void main_body(
    const float* __restrict__ src, const float* __restrict__ A,
    const float* __restrict__ Bw, float* __restrict__ dst,
    int row0, float* s_w, float* s_P2) {

    int tid = threadIdx.x;
    int w = tid >> 5, l = tid & 31;
    constexpr int SH = (R == 4) ? 2 : 3;

    // stage A transposed: s_w[j*H + h] = A[h*R + j]   (H*R floats)
    for (int idx = tid; idx < H * R; idx += MT) {
        int h = idx >> SH, j = idx & (R - 1);
        s_w[j * H + h] = A[idx];
    }
    __syncthreads();

    // ---- Phase 1: 8 warps x 4 rows --------------------------------------
    {
        ull acc[4][R];
#pragma unroll
        for (int i = 0; i < 4; i++)
#pragma unroll
            for (int j = 0; j < R; j++) acc[i][j] = 0ull;

        const ulonglong2* rp0 = (const ulonglong2*)(src + (size_t)(row0 + w * 4 + 0) * H);
        const ulonglong2* rp1 = (const ulonglong2*)(src + (size_t)(row0 + w * 4 + 1) * H);
        const ulonglong2* rp2 = (const ulonglong2*)(src + (size_t)(row0 + w * 4 + 2) * H);
        const ulonglong2* rp3 = (const ulonglong2*)(src + (size_t)(row0 + w * 4 + 3) * H);

#pragma unroll 2
        for (int h4 = l; h4 < H / 4; h4 += 32) {
            ulonglong2 k0 = rp0[h4], k1 = rp1[h4], k2 = rp2[h4], k3 = rp3[h4];
#pragma unroll
            for (int j = 0; j < R; j++) {
                ulonglong2 aq = *(const ulonglong2*)(s_w + j * H + h4 * 4);
                acc[0][j] = fma2(k0.x, aq.x, acc[0][j]);
                acc[0][j] = fma2(k0.y, aq.y, acc[0][j]);
                acc[1][j] = fma2(k1.x, aq.x, acc[1][j]);
                acc[1][j] = fma2(k1.y, aq.y, acc[1][j]);
                acc[2][j] = fma2(k2.x, aq.x, acc[2][j]);
                acc[2][j] = fma2(k2.y, aq.y, acc[2][j]);
                acc[3][j] = fma2(k3.x, aq.x, acc[3][j]);
                acc[3][j] = fma2(k3.y, aq.y, acc[3][j]);
            }
        }
#pragma unroll
        for (int i = 0; i < 4; i++)
#pragma unroll
            for (int j = 0; j < R; j++) {
                float v = pairsum(acc[i][j]);
#pragma unroll
                for (int o = 16; o > 0; o >>= 1) v += __shfl_xor_sync(0xffffffffu, v, o);
                if (l == 0) *(ull*)(s_P2 + ((w * 4 + i) * R + j) * 2) = pack2(v, v);
            }
    }
    __syncthreads();

    // ---- Phase 2: 2 col-halves; B hoisted in regs from GLOBAL ----------
#pragma unroll
    for (int cs = 0; cs < 2; cs++) {
        int col4 = tid + cs * MT;                 // float4 column in [0, 512)
        ull b0[R], b1[R];
#pragma unroll
        for (int j = 0; j < R; j++) {
            float4 bv = __ldg((const float4*)(Bw + (size_t)j * H + col4 * 4));
            b0[j] = pack2(bv.x, bv.y); b1[j] = pack2(bv.z, bv.w);
        }
#pragma unroll 1
        for (int g = 0; g < TILE_R; g += 4) {
            float4 v0 = *((const float4*)(src + (size_t)(row0 + g + 0) * H) + col4);
            float4 v1 = *((const float4*)(src + (size_t)(row0 + g + 1) * H) + col4);
            float4 v2 = *((const float4*)(src + (size_t)(row0 + g + 2) * H) + col4);
            float4 v3 = *((const float4*)(src + (size_t)(row0 + g + 3) * H) + col4);
            ull o0x = pack2(v0.x, v0.y), o0y = pack2(v0.z, v0.w);
            ull o1x = pack2(v1.x, v1.y), o1y = pack2(v1.z, v1.w);
            ull o2x = pack2(v2.x, v2.y), o2y = pack2(v2.z, v2.w);
            ull o3x = pack2(v3.x, v3.y), o3y = pack2(v3.z, v3.w);
#pragma unroll
            for (int j = 0; j < R; j++) {
                ull p0 = *(const ull*)(s_P2 + ((g + 0) * R + j) * 2);
                ull p1 = *(const ull*)(s_P2 + ((g + 1) * R + j) * 2);
                ull p2 = *(const ull*)(s_P2 + ((g + 2) * R + j) * 2);
                ull p3 = *(const ull*)(s_P2 + ((g + 3) * R + j) * 2);
                o0x = fma2(b0[j], p0, o0x); o0y = fma2(b1[j], p0, o0y);
                o1x = fma2(b0[j], p1, o1x); o1y = fma2(b1[j], p1, o1y);
                o2x = fma2(b0[j], p2, o2x); o2y = fma2(b1[j], p2, o2y);
                o3x = fma2(b0[j], p3, o3x); o3y = fma2(b1[j], p3, o3y);
            }
            float r0, r1, r2, r3;
#define STORE_ROW(OX, OY, GG)                                                \
            asm("mov.b64 {%0, %1}, %2;" : "=f"(r0), "=f"(r1) : "l"(OX));     \
            asm("mov.b64 {%0, %1}, %2;" : "=f"(r2), "=f"(r3) : "l"(OY));     \
            *((float4*)(dst + (size_t)(row0 + GG) * H) + col4) =             \
                make_float4(r0, r1, r2, r3);
            STORE_ROW(o0x, o0y, g + 0)
            STORE_ROW(o1x, o1y, g + 1)
            STORE_ROW(o2x, o2y, g + 2)
            STORE_ROW(o3x, o3y, g + 3)
#undef STORE_ROW
        }
    }
}

// ---- cold path: R = 16 (correct, never selected with these inputs) -----
__device__ __noinline__ void main_body16(
    const float* __restrict__ src, const float* __restrict__ A,
    const float* __restrict__ Bw, float* __restrict__ dst,
    int row0, float* s_w, float* s_P2) {

    int tid = threadIdx.x;
    int w = tid >> 5, l = tid & 31;
    constexpr int R = 16;

    // Phase 1 in two j-halves of 8 columns; 8 warps x 2 rows x 2 passes.
    for (int half = 0; half < 2; half++) {
        for (int idx = tid; idx < H * 8; idx += MT) {
            int h = idx >> 3, j = idx & 7;
            s_w[j * H + h] = A[(size_t)h * R + half * 8 + j];
        }
        __syncthreads();
        for (int ps = 0; ps < 2; ps++) {
            int rb = ps * 16 + w * 2;
            ull acc[2][8];
#pragma unroll
            for (int i = 0; i < 2; i++)
#pragma unroll
                for (int j = 0; j < 8; j++) acc[i][j] = 0ull;
            const ulonglong2* rp0 = (const ulonglong2*)(src + (size_t)(row0 + rb + 0) * H);
            const ulonglong2* rp1 = (const ulonglong2*)(src + (size_t)(row0 + rb + 1) * H);
            for (int h4 = l; h4 < H / 4; h4 += 32) {
                ulonglong2 k0 = rp0[h4], k1 = rp1[h4];
#pragma unroll
                for (int j = 0; j < 8; j++) {
                    ulonglong2 aq = *(const ulonglong2*)(s_w + j * H + h4 * 4);
                    acc[0][j] = fma2(k0.x, aq.x, acc[0][j]);
                    acc[0][j] = fma2(k0.y, aq.y, acc[0][j]);
                    acc[1][j] = fma2(k1.x, aq.x, acc[1][j]);
                    acc[1][j] = fma2(k1.y, aq.y, acc[1][j]);
                }
            }
#pragma unroll
            for (int i = 0; i < 2; i++)
#pragma unroll
                for (int j = 0; j < 8; j++) {
                    float v = pairsum(acc[i][j]);
#pragma unroll
                    for (int o = 16; o > 0; o >>= 1) v += __shfl_xor_sync(0xffffffffu, v, o);
                    if (l == 0)
                        *(ull*)(s_P2 + ((rb + i) * R + half * 8 + j) * 2) = pack2(v, v);
                }
        }
        __syncthreads();
    }

    // Phase 2: B straight from global (L1/L2-hit), all 16 j inline.
    for (int cs = 0; cs < 2; cs++) {
        int col4 = tid + cs * MT;
        for (int g = 0; g < TILE_R; g += 2) {
            float4 v0 = *((const float4*)(src + (size_t)(row0 + g + 0) * H) + col4);
            float4 v1 = *((const float4*)(src + (size_t)(row0 + g + 1) * H) + col4);
            ull o0x = pack2(v0.x, v0.y), o0y = pack2(v0.z, v0.w);
            ull o1x = pack2(v1.x, v1.y), o1y = pack2(v1.z, v1.w);
#pragma unroll
            for (int j = 0; j < R; j++) {
                float4 bv = __ldg((const float4*)(Bw + (size_t)j * H + col4 * 4));
                ull bx = pack2(bv.x, bv.y), by = pack2(bv.z, bv.w);
                ull p0 = *(const ull*)(s_P2 + ((g + 0) * R + j) * 2);
                ull p1 = *(const ull*)(s_P2 + ((g + 1) * R + j) * 2);
                o0x = fma2(bx, p0, o0x); o0y = fma2(by, p0, o0y);
                o1x = fma2(bx, p1, o1x); o1y = fma2(by, p1, o1y);
            }
            float r0, r1, r2, r3;
            asm("mov.b64 {%0, %1}, %2;" : "=f"(r0), "=f"(r1) : "l"(o0x));
            asm("mov.b64 {%0, %1}, %2;" : "=f"(r2), "=f"(r3) : "l"(o0y));
            *((float4*)(dst + (size_t)(row0 + g + 0) * H) + col4) = make_float4(r0, r1, r2, r3);
            asm("mov.b64 {%0, %1}, %2;" : "=f"(r0), "=f"(r1) : "l"(o1x));
            asm("mov.b64 {%0, %1}, %2;" : "=f"(r2), "=f"(r3) : "l"(o1y));
            *((float4*)(dst + (size_t)(row0 + g + 1) * H) + col4) = make_float4(r0, r1, r2, r3);
        }
    }
}

// single kernel, uniform branch on g_rank — no dead launches
__global__ void __launch_bounds__(MT, 2)
k_main_all(const float* __restrict__ keys, const float* __restrict__ values,
           const float* __restrict__ kA0, const float* __restrict__ kB0,
           const float* __restrict__ vA0, const float* __restrict__ vB0,
           const float* __restrict__ kA1, const float* __restrict__ kB1,
           const float* __restrict__ vA1, const float* __restrict__ vB1,
           const float* __restrict__ kA2, const float* __restrict__ kB2,
           const float* __restrict__ vA2, const float* __restrict__ vB2,
           float* __restrict__ out) {
    extern __shared__ float smem[];
    float* s_w  = smem;                 // 8*H floats
    float* s_P2 = smem + 8 * H;         // TILE_R*16*2 floats

    int r = g_rank;
    int row0 = blockIdx.x * TILE_R;
    const float* src; float* dst; bool is_k;
    if (row0 < NROWS) { src = keys;   dst = out;                       is_k = true; }
    else { row0 -= NROWS; src = values; dst = out + (size_t)NROWS * H; is_k = false; }

    if (r == 0)
        main_body<4>(src, is_k ? kA0 : vA0, is_k ? kB0 : vB0, dst, row0, s_w, s_P2);
    else if (r == 1)
        main_body<8>(src, is_k ? kA1 : vA1, is_k ? kB1 : vB1, dst, row0, s_w, s_P2);
    else
        main_body16(src, is_k ? kA2 : vA2, is_k ? kB2 : vB2, dst, row0, s_w, s_P2);
}

// ---------------- launch -------------------------------------------------
extern "C" void kernel_launch(void* const* d_in, const int* in_sizes, int n_in,
                              void* d_out, int out_size) {
    const float* keys   = (const float*)d_in[0];
    const float* values = (const float*)d_in[1];
    const float* w1     = (const float*)d_in[2];
    const float* b1     = (const float*)d_in[3];
    const float* w2     = (const float*)d_in[4];
    const float* b2     = (const float*)d_in[5];
    const float* kA0 = (const float*)d_in[6];  const float* kB0 = (const float*)d_in[7];
    const float* vA0 = (const float*)d_in[8];  const float* vB0 = (const float*)d_in[9];
    const float* kA1 = (const float*)d_in[10]; const float* kB1 = (const float*)d_in[11];
    const float* vA1 = (const float*)d_in[12]; const float* vB1 = (const float*)d_in[13];
    const float* kA2 = (const float*)d_in[14]; const float* kB2 = (const float*)d_in[15];
    const float* vA2 = (const float*)d_in[16]; const float* vB2 = (const float*)d_in[17];
    float* out = (float*)d_out;

    const int smem_bytes = (8 * H + TILE_R * 16 * 2) * (int)sizeof(float);  // 69,632
    cudaFuncSetAttribute(k_main_all, cudaFuncAttributeMaxDynamicSharedMemorySize, smem_bytes);

    k_mean_partial<<<dim3(NCHUNK, NB), 512>>>(keys);
    k_gemv1<<<dim3(4, 8, NB), 256>>>(w1);
    k_select<<<1, 256>>>(b1, w2, b2);

    const int grid = (2 * NROWS) / TILE_R;   // 1024 CTAs
    k_main_all<<<grid, MT, smem_bytes>>>(
        keys, values,
        kA0, kB0, vA0, vB0,
        kA1, kB1, vA1, vB1,
        kA2, kB2, vA2, vB2,
        out);
}